// round 16
// baseline (speedup 1.0000x reference)
#include <cuda_runtime.h>

#define NC 4096
#define NA 2048
#define NB (NC + NA)          // 6144 bodies
#define TILE 64
#define TPB 64                // 2 warps
#define NT (NB / TILE)        // 96 tiles: 0..63 circle, 64..95 aabb
#define NCT (NC / TILE)       // 64
#define EPSF 1e-9f

// partial corrections: slice o = "other tile" -> [NT][NB] float2
__device__ float2 g_partial[NT * NB];
__device__ int    g_cnt[NT] = {};

__device__ __forceinline__ float rsq_approx(float x) {
    float r;
    asm("rsqrt.approx.f32 %0, %1;" : "=f"(r) : "f"(x));
    return r;
}
__device__ __forceinline__ void bfly_sum2(float& a, float& b) {
    #pragma unroll
    for (int m = 16; m > 0; m >>= 1) {
        a += __shfl_xor_sync(0xffffffffu, a, m);
        b += __shfl_xor_sync(0xffffffffu, b, m);
    }
}

__global__ void __launch_bounds__(TPB)
collide_kernel(const float* __restrict__ cpos, const float* __restrict__ crad,
               const float* __restrict__ apos, const float* __restrict__ ahalf,
               float* __restrict__ out)
{
    const int bi = blockIdx.y;          // i-tile
    const int bj = blockIdx.x;          // j-tile
    if (bi > bj) return;                // upper triangle: exit immediately

    // j-tile: circle (−x, −y, r, 0) ; aabb (−x, −y, hx, hy)
    __shared__ float4 sj[TILE];
    __shared__ float2 accW[2][TILE];    // per-warp i-side partials
    __shared__ int s_oldA, s_oldB;

    const int tid = threadIdx.x;
    const int w   = tid >> 5;
    const int ln  = tid & 31;
    const bool icirc = (bi < NCT);
    const bool jcirc = (bj < NCT);
    const bool diag  = (bi == bj);

    // stage j-tile (one body per thread), positions negated
    {
        if (jcirc) {
            int j = bj * TILE + tid;
            float2 q = ((const float2*)cpos)[j];
            sj[tid] = make_float4(-q.x, -q.y, crad[j], 0.0f);
        } else {
            int j = bj * TILE + tid - NC;
            float2 q = ((const float2*)apos)[j];
            float2 h = ((const float2*)ahalf)[j];
            sj[tid] = make_float4(-q.x, -q.y, h.x, h.y);
        }
    }

    // i-state: 2 bodies per lane (local index m*32+ln); both warps load all 64
    float pix[2], piy[2], ra2[2], rb2[2];
    #pragma unroll
    for (int m = 0; m < 2; m++) {
        int il = m * 32 + ln;
        if (icirc) {
            int i = bi * TILE + il;
            float2 q = ((const float2*)cpos)[i];
            pix[m] = q.x; piy[m] = q.y;
            ra2[m] = 0.5f * crad[i]; rb2[m] = 0.0f;
        } else {
            int i = bi * TILE + il - NC;
            float2 q = ((const float2*)apos)[i];
            float2 h = ((const float2*)ahalf)[i];
            pix[m] = q.x; piy[m] = q.y;
            ra2[m] = h.x; rb2[m] = h.y;
        }
    }
    __syncthreads();

    float cx[2] = {0, 0}, cy[2] = {0, 0};
    float jrx = 0.0f, jry = 0.0f;
    const int jq = w * 32;               // this warp's j-column base (local)

    if (!diag) {
        if (icirc && jcirc) {
            // ---- circle vs circle, symmetric (off-diag: distinct bodies, no clamp) ----
            #pragma unroll 4
            for (int jj = 0; jj < 32; jj++) {
                float4 b = sj[jq + jj];
                float pxs = 0.0f, pys = 0.0f;
                #pragma unroll
                for (int m = 0; m < 2; m++) {
                    float dx = pix[m] + b.x;
                    float dy = piy[m] + b.y;
                    float d2 = fmaf(dx, dx, dy * dy);
                    float inv = rsq_approx(d2);
                    float hs = fmaf(0.5f, b.z, ra2[m]);     // 0.5*(ri+rj)
                    float s = fmaxf(fmaf(hs, inv, -0.5f), 0.0f);
                    float px = s * dx, py = s * dy;
                    cx[m] += px; cy[m] += py;
                    pxs += px;   pys += py;
                }
                bfly_sum2(pxs, pys);
                if (ln == jj) { jrx -= pxs; jry -= pys; }   // Newton's 3rd law
            }
        } else if (icirc && !jcirc) {
            // ---- circle(i) vs aabb(j), symmetric ----
            #pragma unroll 4
            for (int jj = 0; jj < 32; jj++) {
                float4 b = sj[jq + jj];
                float pxs = 0.0f, pys = 0.0f;
                #pragma unroll
                for (int m = 0; m < 2; m++) {
                    float rx = pix[m] + b.x;                // ci - aj
                    float ry = piy[m] + b.y;
                    float dx = rx - fminf(fmaxf(rx, -b.z), b.z);
                    float dy = ry - fminf(fmaxf(ry, -b.w), b.w);
                    float dd2 = fmaxf(fmaf(dx, dx, dy * dy), EPSF);
                    float inv = rsq_approx(dd2);
                    float s = fmaxf(fmaf(ra2[m], inv, -0.5f), 0.0f);  // ra=0.5*ri
                    float px = s * dx, py = s * dy;
                    cx[m] += px; cy[m] += py;               // push on circle
                    pxs += px;   pys += py;
                }
                bfly_sum2(pxs, pys);
                if (ln == jj) { jrx -= pxs; jry -= pys; }   // opposite on box
            }
        } else {
            // ---- aabb vs aabb, symmetric ----
            #pragma unroll 4
            for (int jj = 0; jj < 32; jj++) {
                float4 b = sj[jq + jj];
                float pxs = 0.0f, pys = 0.0f;
                #pragma unroll
                for (int m = 0; m < 2; m++) {
                    float dax = pix[m] + b.x;
                    float day = piy[m] + b.y;
                    float ovx = (ra2[m] + b.z) - fabsf(dax);
                    float ovy = (rb2[m] + b.w) - fabsf(day);
                    bool hit = (ovx > 0.0f) && (ovy > 0.0f);
                    bool ux  = (ovx <= ovy);
                    float px = (hit && ux)  ? copysignf(0.5f * ovx, dax) : 0.0f;
                    float py = (hit && !ux) ? copysignf(0.5f * ovy, day) : 0.0f;
                    cx[m] += px; cy[m] += py;
                    pxs += px;   pys += py;
                }
                bfly_sum2(pxs, pys);
                if (ln == jj) { jrx -= pxs; jry -= pys; }
            }
        }
    } else {
        // ---- diagonal tile: one-sided, this warp's 32 j-columns, no butterfly ----
        if (icirc) {
            // cc diag: EPS clamp => self-pair contributes exactly 0
            #pragma unroll 4
            for (int jj = 0; jj < 32; jj++) {
                float4 b = sj[jq + jj];
                #pragma unroll
                for (int m = 0; m < 2; m++) {
                    float dx = pix[m] + b.x;
                    float dy = piy[m] + b.y;
                    float d2 = fmaxf(fmaf(dx, dx, dy * dy), EPSF);
                    float inv = rsq_approx(d2);
                    float hs = fmaf(0.5f, b.z, ra2[m]);
                    float s = fmaxf(fmaf(hs, inv, -0.5f), 0.0f);
                    cx[m] = fmaf(s, dx, cx[m]);
                    cy[m] = fmaf(s, dy, cy[m]);
                }
            }
        } else {
            // aa diag: guard self-pair (local index compare)
            #pragma unroll 4
            for (int jj = 0; jj < 32; jj++) {
                float4 b = sj[jq + jj];
                int jl = jq + jj;
                #pragma unroll
                for (int m = 0; m < 2; m++) {
                    int il = m * 32 + ln;
                    float dax = pix[m] + b.x;
                    float day = piy[m] + b.y;
                    float ovx = (ra2[m] + b.z) - fabsf(dax);
                    float ovy = (rb2[m] + b.w) - fabsf(day);
                    bool hit = (ovx > 0.0f) && (ovy > 0.0f) && (il != jl);
                    bool ux  = (ovx <= ovy);
                    cx[m] += (hit && ux)  ? copysignf(0.5f * ovx, dax) : 0.0f;
                    cy[m] += (hit && !ux) ? copysignf(0.5f * ovy, day) : 0.0f;
                }
            }
        }
    }

    // ---- i-side: merge the 2 warps' partial sums (fixed order) ----
    #pragma unroll
    for (int m = 0; m < 2; m++)
        accW[w][m * 32 + ln] = make_float2(cx[m], cy[m]);
    __syncthreads();
    {
        float2 a0 = accW[0][tid], a1 = accW[1][tid];
        g_partial[(size_t)bj * NB + bi * TILE + tid] =
            make_float2(a0.x + a1.x, a0.y + a1.y);
    }
    // ---- j-side: lane ln of warp w owns local column jq+ln ----
    if (!diag)
        g_partial[(size_t)bi * NB + bj * TILE + jq + ln] = make_float2(jrx, jry);

    // ---- counters + fold by last-arriving writer per tile ----
    __threadfence();                       // release all our partial writes
    __syncthreads();
    if (tid == 0) {
        s_oldA = atomicAdd(&g_cnt[bi], 1);
        s_oldB = diag ? -2 : atomicAdd(&g_cnt[bj], 1);
    }
    __syncthreads();

    #pragma unroll
    for (int which = 0; which < 2; which++) {
        int old = (which == 0) ? s_oldA : s_oldB;
        int T   = (which == 0) ? bi : bj;
        if (old == NT - 1) {
            __threadfence();               // acquire: see all 96 slices
            int idx = T * TILE + tid;
            float2 base = (idx < NC) ? ((const float2*)cpos)[idx]
                                     : ((const float2*)apos)[idx - NC];
            float sx = base.x, sy = base.y;
            #pragma unroll 8
            for (int o = 0; o < NT; o++) { // fixed order => deterministic
                float2 v = g_partial[(size_t)o * NB + idx];
                sx += v.x; sy += v.y;
            }
            ((float2*)out)[idx] = make_float2(sx, sy);
            if (tid == 0) g_cnt[T] = 0;    // reset for next graph replay
        }
    }
}

extern "C" void kernel_launch(void* const* d_in, const int* in_sizes, int n_in,
                              void* d_out, int out_size)
{
    const float* cpos  = (const float*)d_in[0];   // [4096,2]
    const float* crad  = (const float*)d_in[1];   // [4096]
    const float* apos  = (const float*)d_in[2];   // [2048,2]
    const float* ahalf = (const float*)d_in[3];   // [2048,2]
    float* out = (float*)d_out;                   // [6144,2]

    dim3 grid(NT, NT);                            // lower triangle works, rest exit
    collide_kernel<<<grid, TPB>>>(cpos, crad, apos, ahalf, out);
}

// round 17
// speedup vs baseline: 1.2551x; 1.2551x over previous
#include <cuda_runtime.h>

#define NC 4096
#define NA 2048
#define NB (NC + NA)          // 6144 bodies
#define TILE 128
#define HALF 64
#define TPB 128               // 4 warps
#define NT (NB / TILE)        // 48 tiles: 0..31 circle, 32..47 aabb
#define NCT (NC / TILE)       // 32
#define NSL (2 * NT)          // 96 slices
#define EPSF 1e-9f

// partial corrections: slice s = 2*otherTile + half -> [NSL][NB] float2
// (entries never written stay zero from static init — correct, replay-stable)
__device__ float2 g_partial[NSL * NB];
__device__ int    g_cnt[NT] = {};

__device__ __forceinline__ float rsq_approx(float x) {
    float r;
    asm("rsqrt.approx.f32 %0, %1;" : "=f"(r) : "f"(x));
    return r;
}
__device__ __forceinline__ void bfly_sum2(float& a, float& b) {
    #pragma unroll
    for (int m = 16; m > 0; m >>= 1) {
        a += __shfl_xor_sync(0xffffffffu, a, m);
        b += __shfl_xor_sync(0xffffffffu, b, m);
    }
}

__global__ void __launch_bounds__(TPB)
collide_kernel(const float* __restrict__ cpos, const float* __restrict__ crad,
               const float* __restrict__ apos, const float* __restrict__ ahalf,
               float* __restrict__ out)
{
    const int bj = blockIdx.x >> 1;     // j-tile
    const int h  = blockIdx.x & 1;      // j-half
    const int bi = blockIdx.y;          // i-tile
    if (bi > bj) return;                // upper triangle: exit immediately

    // j-half-tile: circle (−x, −y, r, 0) ; aabb (−x, −y, hx, hy)
    __shared__ float4 sj[HALF];
    __shared__ float2 accW[4][TILE];    // per-warp i-side partials
    __shared__ int s_oldA, s_oldB;

    const int tid = threadIdx.x;
    const int w   = tid >> 5;
    const int ln  = tid & 31;
    const bool icirc = (bi < NCT);
    const bool jcirc = (bj < NCT);
    const bool diag  = (bi == bj);

    // stage 64 j-bodies (threads 0..63), positions negated
    if (tid < HALF) {
        if (jcirc) {
            int j = bj * TILE + h * HALF + tid;
            float2 q = ((const float2*)cpos)[j];
            sj[tid] = make_float4(-q.x, -q.y, crad[j], 0.0f);
        } else {
            int j = bj * TILE + h * HALF + tid - NC;
            float2 q = ((const float2*)apos)[j];
            float2 hh = ((const float2*)ahalf)[j];
            sj[tid] = make_float4(-q.x, -q.y, hh.x, hh.y);
        }
    }

    // i-state: 4 bodies per lane (local index m*32+ln)
    float pix[4], piy[4], ra4[4], rb4[4];
    #pragma unroll
    for (int m = 0; m < 4; m++) {
        int il = m * 32 + ln;
        if (icirc) {
            int i = bi * TILE + il;
            float2 q = ((const float2*)cpos)[i];
            pix[m] = q.x; piy[m] = q.y;
            ra4[m] = 0.5f * crad[i]; rb4[m] = 0.0f;
        } else {
            int i = bi * TILE + il - NC;
            float2 q = ((const float2*)apos)[i];
            float2 hh = ((const float2*)ahalf)[i];
            pix[m] = q.x; piy[m] = q.y;
            ra4[m] = hh.x; rb4[m] = hh.y;
        }
    }
    __syncthreads();

    float cx[4] = {0,0,0,0}, cy[4] = {0,0,0,0};
    float jrx = 0.0f, jry = 0.0f;
    const int jq = w * 16;               // this warp's 16 j-columns (local in half)

    if (!diag) {
        if (icirc && jcirc) {
            // ---- circle vs circle, symmetric (off-diag: no EPS clamp needed) ----
            #pragma unroll 4
            for (int jj = 0; jj < 16; jj++) {
                float4 b = sj[jq + jj];
                float pxs = 0.0f, pys = 0.0f;
                #pragma unroll
                for (int m = 0; m < 4; m++) {
                    float dx = pix[m] + b.x;
                    float dy = piy[m] + b.y;
                    float d2 = fmaf(dx, dx, dy * dy);
                    float inv = rsq_approx(d2);
                    float hs = fmaf(0.5f, b.z, ra4[m]);     // 0.5*(ri+rj)
                    float s = fmaxf(fmaf(hs, inv, -0.5f), 0.0f);
                    float px = s * dx, py = s * dy;
                    cx[m] += px; cy[m] += py;
                    pxs += px;   pys += py;
                }
                bfly_sum2(pxs, pys);
                if (ln == jj) { jrx = -pxs; jry = -pys; }   // Newton's 3rd law
            }
        } else if (icirc && !jcirc) {
            // ---- circle(i) vs aabb(j), symmetric ----
            #pragma unroll 4
            for (int jj = 0; jj < 16; jj++) {
                float4 b = sj[jq + jj];
                float pxs = 0.0f, pys = 0.0f;
                #pragma unroll
                for (int m = 0; m < 4; m++) {
                    float rx = pix[m] + b.x;                // ci - aj
                    float ry = piy[m] + b.y;
                    float dx = rx - fminf(fmaxf(rx, -b.z), b.z);
                    float dy = ry - fminf(fmaxf(ry, -b.w), b.w);
                    float dd2 = fmaxf(fmaf(dx, dx, dy * dy), EPSF);
                    float inv = rsq_approx(dd2);
                    float s = fmaxf(fmaf(ra4[m], inv, -0.5f), 0.0f);  // ra=0.5*ri
                    float px = s * dx, py = s * dy;
                    cx[m] += px; cy[m] += py;               // push on circle
                    pxs += px;   pys += py;
                }
                bfly_sum2(pxs, pys);
                if (ln == jj) { jrx = -pxs; jry = -pys; }   // opposite on box
            }
        } else {
            // ---- aabb vs aabb, symmetric ----
            #pragma unroll 4
            for (int jj = 0; jj < 16; jj++) {
                float4 b = sj[jq + jj];
                float pxs = 0.0f, pys = 0.0f;
                #pragma unroll
                for (int m = 0; m < 4; m++) {
                    float dax = pix[m] + b.x;
                    float day = piy[m] + b.y;
                    float ovx = (ra4[m] + b.z) - fabsf(dax);
                    float ovy = (rb4[m] + b.w) - fabsf(day);
                    bool hit = (ovx > 0.0f) && (ovy > 0.0f);
                    bool ux  = (ovx <= ovy);
                    float px = (hit && ux)  ? copysignf(0.5f * ovx, dax) : 0.0f;
                    float py = (hit && !ux) ? copysignf(0.5f * ovy, day) : 0.0f;
                    cx[m] += px; cy[m] += py;
                    pxs += px;   pys += py;
                }
                bfly_sum2(pxs, pys);
                if (ln == jj) { jrx = -pxs; jry = -pys; }
            }
        }
    } else {
        // ---- diagonal: one-sided over this warp's 16 j-columns ----
        if (icirc) {
            // cc diag: EPS clamp => self-pair contributes exactly 0
            #pragma unroll 4
            for (int jj = 0; jj < 16; jj++) {
                float4 b = sj[jq + jj];
                #pragma unroll
                for (int m = 0; m < 4; m++) {
                    float dx = pix[m] + b.x;
                    float dy = piy[m] + b.y;
                    float d2 = fmaxf(fmaf(dx, dx, dy * dy), EPSF);
                    float inv = rsq_approx(d2);
                    float hs = fmaf(0.5f, b.z, ra4[m]);
                    float s = fmaxf(fmaf(hs, inv, -0.5f), 0.0f);
                    cx[m] = fmaf(s, dx, cx[m]);
                    cy[m] = fmaf(s, dy, cy[m]);
                }
            }
        } else {
            // aa diag: guard self-pair (local index compare)
            #pragma unroll 4
            for (int jj = 0; jj < 16; jj++) {
                float4 b = sj[jq + jj];
                int jl = h * HALF + jq + jj;
                #pragma unroll
                for (int m = 0; m < 4; m++) {
                    int il = m * 32 + ln;
                    float dax = pix[m] + b.x;
                    float day = piy[m] + b.y;
                    float ovx = (ra4[m] + b.z) - fabsf(dax);
                    float ovy = (rb4[m] + b.w) - fabsf(day);
                    bool hit = (ovx > 0.0f) && (ovy > 0.0f) && (il != jl);
                    bool ux  = (ovx <= ovy);
                    cx[m] += (hit && ux)  ? copysignf(0.5f * ovx, dax) : 0.0f;
                    cy[m] += (hit && !ux) ? copysignf(0.5f * ovy, day) : 0.0f;
                }
            }
        }
    }

    // ---- i-side: merge the 4 warps' partial sums (fixed order) ----
    #pragma unroll
    for (int m = 0; m < 4; m++)
        accW[w][m * 32 + ln] = make_float2(cx[m], cy[m]);
    __syncthreads();
    {
        float2 a0 = accW[0][tid], a1 = accW[1][tid];
        float2 a2 = accW[2][tid], a3 = accW[3][tid];
        g_partial[(size_t)(2 * bj + h) * NB + bi * TILE + tid] =
            make_float2(((a0.x + a1.x) + a2.x) + a3.x,
                        ((a0.y + a1.y) + a2.y) + a3.y);
    }
    // ---- j-side: lane ln<16 of warp w owns local column jq+ln ----
    if (!diag && ln < 16)
        g_partial[(size_t)(2 * bi + h) * NB + bj * TILE + h * HALF + jq + ln] =
            make_float2(jrx, jry);

    // ---- counters + fold by last-arriving writer per tile (96 writers/tile) ----
    __threadfence();                       // release all our partial writes
    __syncthreads();
    if (tid == 0) {
        s_oldA = atomicAdd(&g_cnt[bi], 1);
        s_oldB = diag ? -2 : atomicAdd(&g_cnt[bj], 1);
    }
    __syncthreads();

    #pragma unroll
    for (int which = 0; which < 2; which++) {
        int old = (which == 0) ? s_oldA : s_oldB;
        int T   = (which == 0) ? bi : bj;
        if (old == NSL - 1) {
            __threadfence();               // acquire: see all 96 slices
            int idx = T * TILE + tid;
            float2 base = (idx < NC) ? ((const float2*)cpos)[idx]
                                     : ((const float2*)apos)[idx - NC];
            float sx = base.x, sy = base.y;
            #pragma unroll 8
            for (int s = 0; s < NSL; s++) { // fixed order => deterministic
                float2 v = g_partial[(size_t)s * NB + idx];
                sx += v.x; sy += v.y;
            }
            ((float2*)out)[idx] = make_float2(sx, sy);
            if (tid == 0) g_cnt[T] = 0;    // reset for next graph replay
        }
    }
}

extern "C" void kernel_launch(void* const* d_in, const int* in_sizes, int n_in,
                              void* d_out, int out_size)
{
    const float* cpos  = (const float*)d_in[0];   // [4096,2]
    const float* crad  = (const float*)d_in[1];   // [4096]
    const float* apos  = (const float*)d_in[2];   // [2048,2]
    const float* ahalf = (const float*)d_in[3];   // [2048,2]
    float* out = (float*)d_out;                   // [6144,2]

    dim3 grid(2 * NT, NT);                        // (j-tile, half) x i-tile
    collide_kernel<<<grid, TPB>>>(cpos, crad, apos, ahalf, out);
}